// round 2
// baseline (speedup 1.0000x reference)
#include <cuda_runtime.h>
#include <cuda_bf16.h>
#include <cstdint>

// ---------------------------------------------------------------------------
// BiMamba refiner block, fp32.
// B=2, T=4, N=196 -> L=784, M=B*L=1568. D_MODEL=768, D_INNER=1536,
// D_STATE=16, DT_RANK=48, D_CONV=4.
// ---------------------------------------------------------------------------

#define BB      2
#define TT      4
#define NP      196
#define LL      784            // TT*NP
#define MM      1568           // BB*LL
#define CM      768            // D_MODEL
#define DI      1536           // D_INNER
#define DS      16             // D_STATE
#define DR      48             // DT_RANK
#define DCONV   4

// ---------------- scratch (static __device__, no allocations) --------------
__device__ float g_xn  [2 * MM * CM];        // rmsnormed input per dir (dir coords)
__device__ float g_xz  [2 * MM * 2 * DI];    // in_proj output (xb | z)
__device__ float g_xb  [2 * MM * DI];        // conv+silu output
__device__ float g_xdbl[2 * MM * 80];        // x_proj output (dt_raw|B|C)
__device__ float g_dt  [2 * MM * DI];        // softplus(dt)
__device__ float g_y   [2 * MM * DI];        // scan output * silu(z)
__device__ float g_out [MM * 2 * CM];        // interleaved [m][dir][CM] (orig coords)
__device__ float g_comb[MM * CM];            // gate-combined
__device__ float g_A   [2 * DI * DS];        // -exp(A_log)
__device__ int   g_arith;                    // 1 if every A row is arithmetic

// flip map for dir 1 (involution): l -> (T-1-t)*N + n
__device__ __forceinline__ int map_row(int l, int dir) {
    if (dir == 0) return l;
    int t = l / NP, n = l - t * NP;
    return (TT - 1 - t) * NP + n;
}

__device__ __forceinline__ float sigmoidf_(float v) {
    return 1.0f / (1.0f + __expf(-v));
}
__device__ __forceinline__ float siluf_(float v) {
    return v * sigmoidf_(v);
}

// ---------------------------------------------------------------------------
// setup: A = -exp(A_log); check arithmetic progression per row
// ---------------------------------------------------------------------------
__global__ void setup_A_kernel(const float* __restrict__ A_log) {
    int i = blockIdx.x * blockDim.x + threadIdx.x;
    if (i < 2 * DI * DS) g_A[i] = -expf(A_log[i]);
}

__global__ void check_arith_kernel() {
    __shared__ int bad;
    if (threadIdx.x == 0) bad = 0;
    __syncthreads();
    for (int row = threadIdx.x; row < 2 * DI; row += blockDim.x) {
        const float* a = &g_A[row * DS];
        float a0 = a[0], da = a[1] - a[0];
        for (int n = 2; n < DS; n++) {
            float expect = a0 + n * da;
            if (fabsf(a[n] - expect) > 1e-4f * (1.0f + fabsf(a[n]))) { bad = 1; break; }
        }
    }
    __syncthreads();
    if (threadIdx.x == 0) g_arith = bad ? 0 : 1;
}

// ---------------------------------------------------------------------------
// RMSNorm (gather through flip map for dir 1)
// grid: 2*MM blocks of 256 threads (one token each)
// ---------------------------------------------------------------------------
__global__ void rmsnorm_kernel(const float* __restrict__ x,
                               const float* __restrict__ norm_w) {
    int gid = blockIdx.x;                  // dir*MM + b*LL + l
    int dir = gid / MM;
    int rem = gid - dir * MM;              // b*LL + l
    int b   = rem / LL, l = rem - b * LL;
    int lo  = map_row(l, dir);
    const float* row = x + (size_t)(b * LL + lo) * CM;

    float s = 0.f;
    for (int c = threadIdx.x; c < CM; c += blockDim.x) {
        float v = row[c];
        s += v * v;
    }
    // block reduce
    __shared__ float warp_s[8];
    for (int off = 16; off > 0; off >>= 1) s += __shfl_down_sync(0xffffffffu, s, off);
    if ((threadIdx.x & 31) == 0) warp_s[threadIdx.x >> 5] = s;
    __syncthreads();
    if (threadIdx.x < 8) {
        float t = warp_s[threadIdx.x];
        for (int off = 4; off > 0; off >>= 1) t += __shfl_down_sync(0xffu, t, off);
        if (threadIdx.x == 0) warp_s[0] = t;
    }
    __syncthreads();
    float scale = rsqrtf(warp_s[0] / (float)CM + 1e-5f);

    float* dst = g_xn + (size_t)gid * CM;
    const float* nw = norm_w + dir * CM;
    for (int c = threadIdx.x; c < CM; c += blockDim.x)
        dst[c] = row[c] * scale * nw[c];
}

// ---------------------------------------------------------------------------
// generic fp32 GEMM:  C[M,N] = A[M,K] * W[N,K]^T   (W row-major N x K)
// 128x128x8 tile, 256 threads, 8x8 per thread. Epilogues by template.
// ---------------------------------------------------------------------------
#define EPI_STORE    0
#define EPI_SOFTPLUS 1
#define EPI_RESID    2   // C := g_out interleaved, residual x + flip scatter
#define EPI_GATE     3   // sigmoid gate combine (aux = g_out)
#define EPI_BIAS     4

template <int EPI>
__global__ void __launch_bounds__(256, 2)
gemm_kernel(const float* __restrict__ A, int lda,
            const float* __restrict__ W,
            float* __restrict__ C, int ldc,
            int M, int N, int K,
            const float* __restrict__ bias,
            const float* __restrict__ aux,
            int dir) {
    __shared__ float As[8][128];
    __shared__ float Bs[8][128];

    const int tid = threadIdx.x;
    const int m0 = blockIdx.y * 128;
    const int n0 = blockIdx.x * 128;
    const int tx = tid & 15;        // 0..15 -> n
    const int ty = tid >> 4;        // 0..15 -> m

    const int lm = tid >> 1;        // 0..127
    const int lk = (tid & 1) * 4;   // 0 or 4

    float acc[8][8];
#pragma unroll
    for (int i = 0; i < 8; i++)
#pragma unroll
        for (int j = 0; j < 8; j++) acc[i][j] = 0.f;

    for (int k0 = 0; k0 < K; k0 += 8) {
        float4 av = make_float4(0.f, 0.f, 0.f, 0.f);
        int am = m0 + lm;
        if (am < M) av = *(const float4*)&A[(size_t)am * lda + k0 + lk];
        As[lk + 0][lm] = av.x; As[lk + 1][lm] = av.y;
        As[lk + 2][lm] = av.z; As[lk + 3][lm] = av.w;

        float4 wv = make_float4(0.f, 0.f, 0.f, 0.f);
        int wn = n0 + lm;
        if (wn < N) wv = *(const float4*)&W[(size_t)wn * K + k0 + lk];
        Bs[lk + 0][lm] = wv.x; Bs[lk + 1][lm] = wv.y;
        Bs[lk + 2][lm] = wv.z; Bs[lk + 3][lm] = wv.w;
        __syncthreads();

#pragma unroll
        for (int k = 0; k < 8; k++) {
            float4 a0v = *(const float4*)&As[k][ty * 8];
            float4 a1v = *(const float4*)&As[k][ty * 8 + 4];
            float4 b0v = *(const float4*)&Bs[k][tx * 8];
            float4 b1v = *(const float4*)&Bs[k][tx * 8 + 4];
            float a[8] = {a0v.x, a0v.y, a0v.z, a0v.w, a1v.x, a1v.y, a1v.z, a1v.w};
            float bfrag[8] = {b0v.x, b0v.y, b0v.z, b0v.w, b1v.x, b1v.y, b1v.z, b1v.w};
#pragma unroll
            for (int i = 0; i < 8; i++)
#pragma unroll
                for (int j = 0; j < 8; j++) acc[i][j] = fmaf(a[i], bfrag[j], acc[i][j]);
        }
        __syncthreads();
    }

#pragma unroll
    for (int i = 0; i < 8; i++) {
        int m = m0 + ty * 8 + i;
        if (m >= M) continue;
#pragma unroll
        for (int j = 0; j < 8; j++) {
            int n = n0 + tx * 8 + j;
            if (n >= N) continue;
            float v = acc[i][j];
            if (EPI == EPI_STORE) {
                C[(size_t)m * ldc + n] = v;
            } else if (EPI == EPI_SOFTPLUS) {
                v += bias[n];
                // softplus(v) = log1p(exp(v)), stable
                float sp = (v > 20.f) ? v : log1pf(__expf(v));
                C[(size_t)m * ldc + n] = sp;
            } else if (EPI == EPI_RESID) {
                int b = m / LL, l = m - b * LL;
                int lo = map_row(l, dir);
                int row = b * LL + lo;
                // interleaved out: [row][dir][CM]; residual = x[row][n]
                C[((size_t)row * 2 + dir) * CM + n] = aux[(size_t)row * CM + n] + v;
            } else if (EPI == EPI_GATE) {
                float g  = sigmoidf_(v + bias[n]);
                float of = aux[(size_t)m * (2 * CM) + n];
                float ob = aux[(size_t)m * (2 * CM) + CM + n];
                C[(size_t)m * ldc + n] = g * of + (1.f - g) * ob;
            } else { // EPI_BIAS
                C[(size_t)m * ldc + n] = v + bias[n];
            }
        }
    }
}

// ---------------------------------------------------------------------------
// causal depthwise conv (k=4) + bias + SiLU, reading xb half of g_xz
// ---------------------------------------------------------------------------
__global__ void conv_silu_kernel(const float* __restrict__ conv_w,
                                 const float* __restrict__ conv_b) {
    int idx = blockIdx.x * blockDim.x + threadIdx.x;
    if (idx >= 2 * MM * DI) return;
    int d = idx % DI;
    int r = idx / DI;               // dir*MM + b*LL + l
    int dir = r / MM;
    int l = r % LL;

    const float* w = conv_w + (size_t)(dir * DI + d) * DCONV;
    float acc = conv_b[dir * DI + d];
#pragma unroll
    for (int j = 0; j < DCONV; j++) {
        int ls = l - (DCONV - 1) + j;
        if (ls >= 0)
            acc = fmaf(w[j], g_xz[(size_t)(r - (DCONV - 1) + j) * (2 * DI) + d], acc);
    }
    g_xb[(size_t)r * DI + d] = siluf_(acc);
}

// ---------------------------------------------------------------------------
// selective scan + y *= silu(z). One thread per channel, 16 states in regs.
// Fast path: A row arithmetic -> dA powers via 2 exps/step.
// grid (6, B, 2), block 256.
// ---------------------------------------------------------------------------
__global__ void __launch_bounds__(256, 4)
scan_kernel(const float* __restrict__ Dp) {
    int d   = blockIdx.x * blockDim.x + threadIdx.x;   // 0..DI-1
    int b   = blockIdx.y;
    int dir = blockIdx.z;
    if (d >= DI) return;

    const float* Arow = &g_A[(dir * DI + d) * DS];
    float a0 = Arow[0];
    float da = Arow[1] - Arow[0];
    float Ar[DS];
    bool arith = (g_arith != 0);
    if (!arith) {
#pragma unroll
        for (int n = 0; n < DS; n++) Ar[n] = Arow[n];
    }

    float h[DS];
#pragma unroll
    for (int n = 0; n < DS; n++) h[n] = 0.f;

    float Dd = Dp[dir * DI + d];
    size_t r0 = (size_t)dir * MM + (size_t)b * LL;

    for (int l = 0; l < LL; l++) {
        size_t r = r0 + l;
        float u  = g_xb[r * DI + d];
        float dt = g_dt[r * DI + d];
        const float4* BC = (const float4*)(&g_xdbl[r * 80 + DR]);
        float4 Bv0 = __ldg(&BC[0]), Bv1 = __ldg(&BC[1]);
        float4 Bv2 = __ldg(&BC[2]), Bv3 = __ldg(&BC[3]);
        float4 Cv0 = __ldg(&BC[4]), Cv1 = __ldg(&BC[5]);
        float4 Cv2 = __ldg(&BC[6]), Cv3 = __ldg(&BC[7]);
        float Bl[DS] = {Bv0.x, Bv0.y, Bv0.z, Bv0.w, Bv1.x, Bv1.y, Bv1.z, Bv1.w,
                        Bv2.x, Bv2.y, Bv2.z, Bv2.w, Bv3.x, Bv3.y, Bv3.z, Bv3.w};
        float Cl[DS] = {Cv0.x, Cv0.y, Cv0.z, Cv0.w, Cv1.x, Cv1.y, Cv1.z, Cv1.w,
                        Cv2.x, Cv2.y, Cv2.z, Cv2.w, Cv3.x, Cv3.y, Cv3.z, Cv3.w};

        float du = dt * u;
        float yv = 0.f;
        if (arith) {
            float p  = __expf(dt * a0);
            float rr = __expf(dt * da);
#pragma unroll
            for (int n = 0; n < DS; n++) {
                h[n] = fmaf(p, h[n], du * Bl[n]);
                yv   = fmaf(h[n], Cl[n], yv);
                p *= rr;
            }
        } else {
#pragma unroll
            for (int n = 0; n < DS; n++) {
                float p = __expf(dt * Ar[n]);
                h[n] = fmaf(p, h[n], du * Bl[n]);
                yv   = fmaf(h[n], Cl[n], yv);
            }
        }
        yv = fmaf(u, Dd, yv);
        float z = g_xz[r * (2 * DI) + DI + d];
        g_y[r * DI + d] = yv * siluf_(z);
    }
}

// ---------------------------------------------------------------------------
// host launcher
// ---------------------------------------------------------------------------
static inline dim3 gemm_grid(int M, int N) {
    return dim3((N + 127) / 128, (M + 127) / 128);
}

extern "C" void kernel_launch(void* const* d_in, const int* in_sizes, int n_in,
                              void* d_out, int out_size) {
    const float* x         = (const float*)d_in[0];
    const float* norm_w    = (const float*)d_in[1];
    const float* in_proj_w = (const float*)d_in[2];   // (2, 3072, 768)
    const float* conv_w    = (const float*)d_in[3];   // (2, 1536, 4)
    const float* conv_b    = (const float*)d_in[4];
    const float* x_proj_w  = (const float*)d_in[5];   // (2, 80, 1536)
    const float* dt_proj_w = (const float*)d_in[6];   // (2, 1536, 48)
    const float* dt_proj_b = (const float*)d_in[7];
    const float* A_log     = (const float*)d_in[8];   // (2, 1536, 16)
    const float* Dp        = (const float*)d_in[9];
    const float* mix_out_w = (const float*)d_in[10];  // (2, 768, 1536)
    const float* gate_w    = (const float*)d_in[11];  // (768, 1536)
    const float* gate_b    = (const float*)d_in[12];
    const float* proj_w    = (const float*)d_in[13];  // (768, 768)
    const float* proj_b    = (const float*)d_in[14];
    float* out = (float*)d_out;

    float *xn, *xz, *xb, *xdbl, *dt, *y, *o_out, *comb;
    cudaGetSymbolAddress((void**)&xn,   g_xn);
    cudaGetSymbolAddress((void**)&xz,   g_xz);
    cudaGetSymbolAddress((void**)&xb,   g_xb);
    cudaGetSymbolAddress((void**)&xdbl, g_xdbl);
    cudaGetSymbolAddress((void**)&dt,   g_dt);
    cudaGetSymbolAddress((void**)&y,    g_y);
    cudaGetSymbolAddress((void**)&o_out,g_out);
    cudaGetSymbolAddress((void**)&comb, g_comb);

    // A matrix + structure check
    setup_A_kernel<<<(2 * DI * DS + 255) / 256, 256>>>(A_log);
    check_arith_kernel<<<1, 256>>>();

    // RMSNorm (both dirs)
    rmsnorm_kernel<<<2 * MM, 256>>>(x, norm_w);

    for (int dir = 0; dir < 2; dir++) {
        // in_proj: (1568x768) @ (3072x768)^T -> xz
        gemm_kernel<EPI_STORE><<<gemm_grid(MM, 2 * DI), 256>>>(
            xn + (size_t)dir * MM * CM, CM,
            in_proj_w + (size_t)dir * 2 * DI * CM,
            xz + (size_t)dir * MM * 2 * DI, 2 * DI,
            MM, 2 * DI, CM, nullptr, nullptr, dir);
    }

    // conv + silu (reads g_xz xb-half, both dirs)
    conv_silu_kernel<<<(2 * MM * DI + 255) / 256, 256>>>(conv_w, conv_b);

    for (int dir = 0; dir < 2; dir++) {
        // x_proj: (1568x1536) @ (80x1536)^T -> xdbl
        gemm_kernel<EPI_STORE><<<gemm_grid(MM, 80), 256>>>(
            xb + (size_t)dir * MM * DI, DI,
            x_proj_w + (size_t)dir * 80 * DI,
            xdbl + (size_t)dir * MM * 80, 80,
            MM, 80, DI, nullptr, nullptr, dir);

        // dt_proj + softplus: (1568x48) @ (1536x48)^T -> dt
        gemm_kernel<EPI_SOFTPLUS><<<gemm_grid(MM, DI), 256>>>(
            xdbl + (size_t)dir * MM * 80, 80,
            dt_proj_w + (size_t)dir * DI * DR,
            dt + (size_t)dir * MM * DI, DI,
            MM, DI, DR, dt_proj_b + dir * DI, nullptr, dir);
    }

    // selective scan + y*silu(z) (both dirs)
    scan_kernel<<<dim3(DI / 256, BB, 2), 256>>>(Dp);

    for (int dir = 0; dir < 2; dir++) {
        // out_proj + residual + flip-scatter -> g_out interleaved
        gemm_kernel<EPI_RESID><<<gemm_grid(MM, CM), 256>>>(
            y + (size_t)dir * MM * DI, DI,
            mix_out_w + (size_t)dir * CM * DI,
            o_out, 0,
            MM, CM, DI, nullptr, x, dir);
    }

    // gate GEMM + sigmoid combine -> comb
    gemm_kernel<EPI_GATE><<<gemm_grid(MM, CM), 256>>>(
        o_out, 2 * CM, gate_w, comb, CM,
        MM, CM, 2 * CM, gate_b, o_out, 0);

    // final projection + bias -> d_out
    gemm_kernel<EPI_BIAS><<<gemm_grid(MM, CM), 256>>>(
        comb, CM, proj_w, out, CM,
        MM, CM, CM, proj_b, nullptr, 0);

    (void)in_sizes; (void)n_in; (void)out_size;
}

// round 3
// speedup vs baseline: 1.5142x; 1.5142x over previous
#include <cuda_runtime.h>
#include <cuda_bf16.h>
#include <cstdint>

// ---------------------------------------------------------------------------
// BiMamba refiner block, fp32, round 2: double-buffered SIMT GEMMs,
// shape-matched tiles, split-K for the skinny x_proj GEMM, dirs in gridDim.z.
// B=2, T=4, N=196 -> L=784, M=B*L=1568. D_MODEL=768, D_INNER=1536,
// D_STATE=16, DT_RANK=48, D_CONV=4.
// ---------------------------------------------------------------------------

#define BB      2
#define TT      4
#define NP      196
#define LL      784            // TT*NP
#define MM      1568           // BB*LL
#define CM      768            // D_MODEL
#define DI      1536           // D_INNER
#define DS      16             // D_STATE
#define DR      48             // DT_RANK
#define DCONV   4

// ---------------- scratch (static __device__, no allocations) --------------
__device__ float g_xn  [2 * MM * CM];        // rmsnormed input per dir (dir coords)
__device__ float g_xz  [2 * MM * 2 * DI];    // in_proj output (xb | z)
__device__ float g_xb  [2 * MM * DI];        // conv+silu output
__device__ float g_xdbl[2 * MM * 80];        // x_proj output (dt_raw|B|C)
__device__ float g_dt  [2 * MM * DI];        // softplus(dt)
__device__ float g_y   [2 * MM * DI];        // scan output * silu(z)
__device__ float g_out [MM * 2 * CM];        // interleaved [m][dir][CM] (orig coords)
__device__ float g_comb[MM * CM];            // gate-combined
__device__ float g_A   [2 * DI * DS];        // -exp(A_log)
__device__ int   g_arith;                    // 1 if every A row is arithmetic

// flip map for dir 1 (involution): l -> (T-1-t)*N + n
__device__ __forceinline__ int map_row(int l, int dir) {
    if (dir == 0) return l;
    int t = l / NP, n = l - t * NP;
    return (TT - 1 - t) * NP + n;
}

__device__ __forceinline__ float sigmoidf_(float v) {
    return 1.0f / (1.0f + __expf(-v));
}
__device__ __forceinline__ float siluf_(float v) {
    return v * sigmoidf_(v);
}

// ---------------------------------------------------------------------------
// setup: A = -exp(A_log); check arithmetic progression per row
// ---------------------------------------------------------------------------
__global__ void setup_A_kernel(const float* __restrict__ A_log) {
    int i = blockIdx.x * blockDim.x + threadIdx.x;
    if (i < 2 * DI * DS) g_A[i] = -expf(A_log[i]);
}

__global__ void check_arith_kernel() {
    __shared__ int bad;
    if (threadIdx.x == 0) bad = 0;
    __syncthreads();
    for (int row = threadIdx.x; row < 2 * DI; row += blockDim.x) {
        const float* a = &g_A[row * DS];
        float a0 = a[0], da = a[1] - a[0];
        for (int n = 2; n < DS; n++) {
            float expect = a0 + n * da;
            if (fabsf(a[n] - expect) > 1e-4f * (1.0f + fabsf(a[n]))) { bad = 1; break; }
        }
    }
    __syncthreads();
    if (threadIdx.x == 0) g_arith = bad ? 0 : 1;
}

// ---------------------------------------------------------------------------
// RMSNorm (gather through flip map for dir 1)
// ---------------------------------------------------------------------------
__global__ void rmsnorm_kernel(const float* __restrict__ x,
                               const float* __restrict__ norm_w) {
    int gid = blockIdx.x;                  // dir*MM + b*LL + l
    int dir = gid / MM;
    int rem = gid - dir * MM;
    int b   = rem / LL, l = rem - b * LL;
    int lo  = map_row(l, dir);
    const float* row = x + (size_t)(b * LL + lo) * CM;

    float s = 0.f;
    for (int c = threadIdx.x; c < CM; c += blockDim.x) {
        float v = row[c];
        s += v * v;
    }
    __shared__ float warp_s[8];
    for (int off = 16; off > 0; off >>= 1) s += __shfl_down_sync(0xffffffffu, s, off);
    if ((threadIdx.x & 31) == 0) warp_s[threadIdx.x >> 5] = s;
    __syncthreads();
    if (threadIdx.x < 8) {
        float t = warp_s[threadIdx.x];
        for (int off = 4; off > 0; off >>= 1) t += __shfl_down_sync(0xffu, t, off);
        if (threadIdx.x == 0) warp_s[0] = t;
    }
    __syncthreads();
    float scale = rsqrtf(warp_s[0] / (float)CM + 1e-5f);

    float* dst = g_xn + (size_t)gid * CM;
    const float* nw = norm_w + dir * CM;
    for (int c = threadIdx.x; c < CM; c += blockDim.x)
        dst[c] = row[c] * scale * nw[c];
}

// ---------------------------------------------------------------------------
// templated fp32 GEMM:  C[M,N] = A[M,K] * W[N,K]^T  (W row-major N x K)
// double-buffered smem, TK=16, 256 threads (16x16), RM=TM/16 x RN=TN/16
// per-thread micro-tile. gridDim.z = dirs * KS (split-K); KS>1 -> atomicAdd.
// ---------------------------------------------------------------------------
#define EPI_STORE    0
#define EPI_SOFTPLUS 1
#define EPI_RESID    2   // write g_out interleaved, residual x + flip scatter
#define EPI_GATE     3   // sigmoid gate combine (aux = g_out)
#define EPI_BIAS     4

template <int TM, int TN, int TK, int EPI, int KS>
__global__ void __launch_bounds__(256, 2)
gemm_t(const float* __restrict__ Ab, int lda, size_t sA,
       const float* __restrict__ Wb, size_t sW,
       float* __restrict__ Cb, int ldc, size_t sC,
       int M, int N, int K,
       const float* __restrict__ biasb, size_t sBias,
       const float* __restrict__ aux) {
    constexpr int RM = TM / 16;
    constexpr int RN = TN / 16;
    constexpr int A4 = TM * TK / 4;          // float4 count in A tile
    constexpr int B4 = TN * TK / 4;
    constexpr int RA = (A4 + 255) / 256;
    constexpr int RB = (B4 + 255) / 256;

    __shared__ float As[2][TK][TM + 4];
    __shared__ float Bs[2][TK][TN + 4];

    const int t  = threadIdx.x;
    const int tx = t & 15;
    const int ty = t >> 4;
    const int m0 = blockIdx.y * TM;
    const int n0 = blockIdx.x * TN;

    const int z = blockIdx.z;
    const int dir   = z / KS;
    const int split = z % KS;

    const float* A = Ab + (size_t)dir * sA;
    const float* W = Wb + (size_t)dir * sW;
    float*       C = Cb + (size_t)dir * sC;
    const float* bias = biasb ? biasb + (size_t)dir * sBias : nullptr;

    const int Kpart = K / KS;
    const int kbeg  = split * Kpart;
    const int nk    = Kpart / TK;

    float4 ra[RA], rb[RB];

    auto gload = [&](int k0) {
#pragma unroll
        for (int i = 0; i < RA; i++) {
            int idx = t + i * 256;
            float4 v = make_float4(0.f, 0.f, 0.f, 0.f);
            if (idx < A4) {
                int m = idx / (TK / 4), kq = idx % (TK / 4);
                int gm = m0 + m;
                if (gm < M) v = *(const float4*)&A[(size_t)gm * lda + k0 + kq * 4];
            }
            ra[i] = v;
        }
#pragma unroll
        for (int i = 0; i < RB; i++) {
            int idx = t + i * 256;
            float4 v = make_float4(0.f, 0.f, 0.f, 0.f);
            if (idx < B4) {
                int n = idx / (TK / 4), kq = idx % (TK / 4);
                int gn = n0 + n;
                if (gn < N) v = *(const float4*)&W[(size_t)gn * K + k0 + kq * 4];
            }
            rb[i] = v;
        }
    };
    auto sstore = [&](int s) {
#pragma unroll
        for (int i = 0; i < RA; i++) {
            int idx = t + i * 256;
            if (idx < A4) {
                int m = idx / (TK / 4), kq = (idx % (TK / 4)) * 4;
                As[s][kq + 0][m] = ra[i].x; As[s][kq + 1][m] = ra[i].y;
                As[s][kq + 2][m] = ra[i].z; As[s][kq + 3][m] = ra[i].w;
            }
        }
#pragma unroll
        for (int i = 0; i < RB; i++) {
            int idx = t + i * 256;
            if (idx < B4) {
                int n = idx / (TK / 4), kq = (idx % (TK / 4)) * 4;
                Bs[s][kq + 0][n] = rb[i].x; Bs[s][kq + 1][n] = rb[i].y;
                Bs[s][kq + 2][n] = rb[i].z; Bs[s][kq + 3][n] = rb[i].w;
            }
        }
    };

    float acc[RM][RN];
#pragma unroll
    for (int i = 0; i < RM; i++)
#pragma unroll
        for (int j = 0; j < RN; j++) acc[i][j] = 0.f;

    gload(kbeg);
    sstore(0);
    __syncthreads();

    int cur = 0;
    for (int kt = 0; kt < nk; kt++) {
        if (kt + 1 < nk) gload(kbeg + (kt + 1) * TK);
#pragma unroll
        for (int k = 0; k < TK; k++) {
            float af[RM], bf[RN];
#pragma unroll
            for (int i = 0; i < RM; i++) af[i] = As[cur][k][ty * RM + i];
#pragma unroll
            for (int j = 0; j < RN; j++) bf[j] = Bs[cur][k][tx * RN + j];
#pragma unroll
            for (int i = 0; i < RM; i++)
#pragma unroll
                for (int j = 0; j < RN; j++)
                    acc[i][j] = fmaf(af[i], bf[j], acc[i][j]);
        }
        __syncthreads();
        if (kt + 1 < nk) {
            sstore(cur ^ 1);
            __syncthreads();
            cur ^= 1;
        }
    }

    // epilogue
#pragma unroll
    for (int i = 0; i < RM; i++) {
        int m = m0 + ty * RM + i;
        if (m >= M) continue;
#pragma unroll
        for (int j = 0; j < RN; j++) {
            int n = n0 + tx * RN + j;
            if (n >= N) continue;
            float v = acc[i][j];
            if (KS > 1) {
                atomicAdd(&C[(size_t)m * ldc + n], v);
            } else if (EPI == EPI_STORE) {
                C[(size_t)m * ldc + n] = v;
            } else if (EPI == EPI_SOFTPLUS) {
                v += bias[n];
                float sp = (v > 20.f) ? v : log1pf(__expf(v));
                C[(size_t)m * ldc + n] = sp;
            } else if (EPI == EPI_RESID) {
                int b = m / LL, l = m - b * LL;
                int lo = map_row(l, dir);
                int row = b * LL + lo;
                C[((size_t)row * 2 + dir) * CM + n] = aux[(size_t)row * CM + n] + v;
            } else if (EPI == EPI_GATE) {
                float g  = sigmoidf_(v + bias[n]);
                float of = aux[(size_t)m * (2 * CM) + n];
                float ob = aux[(size_t)m * (2 * CM) + CM + n];
                C[(size_t)m * ldc + n] = g * of + (1.f - g) * ob;
            } else { // EPI_BIAS
                C[(size_t)m * ldc + n] = v + bias[n];
            }
        }
    }
}

// ---------------------------------------------------------------------------
// causal depthwise conv (k=4) + bias + SiLU, reading xb half of g_xz
// ---------------------------------------------------------------------------
__global__ void conv_silu_kernel(const float* __restrict__ conv_w,
                                 const float* __restrict__ conv_b) {
    int idx = blockIdx.x * blockDim.x + threadIdx.x;
    if (idx >= 2 * MM * DI) return;
    int d = idx % DI;
    int r = idx / DI;               // dir*MM + b*LL + l
    int dir = r / MM;
    int l = r % LL;

    const float* w = conv_w + (size_t)(dir * DI + d) * DCONV;
    float acc = conv_b[dir * DI + d];
#pragma unroll
    for (int j = 0; j < DCONV; j++) {
        int ls = l - (DCONV - 1) + j;
        if (ls >= 0)
            acc = fmaf(w[j], g_xz[(size_t)(r - (DCONV - 1) + j) * (2 * DI) + d], acc);
    }
    g_xb[(size_t)r * DI + d] = siluf_(acc);
}

// ---------------------------------------------------------------------------
// selective scan + y *= silu(z). One thread per channel, 16 states in regs.
// grid (12, B, 2), block 128 -> 48 CTAs spread over more SMs.
// ---------------------------------------------------------------------------
__global__ void __launch_bounds__(128, 8)
scan_kernel(const float* __restrict__ Dp) {
    int d   = blockIdx.x * blockDim.x + threadIdx.x;   // 0..DI-1
    int b   = blockIdx.y;
    int dir = blockIdx.z;
    if (d >= DI) return;

    const float* Arow = &g_A[(dir * DI + d) * DS];
    float a0 = Arow[0];
    float da = Arow[1] - Arow[0];
    float Ar[DS];
    bool arith = (g_arith != 0);
    if (!arith) {
#pragma unroll
        for (int n = 0; n < DS; n++) Ar[n] = Arow[n];
    }

    float h[DS];
#pragma unroll
    for (int n = 0; n < DS; n++) h[n] = 0.f;

    float Dd = Dp[dir * DI + d];
    size_t r0 = (size_t)dir * MM + (size_t)b * LL;

    for (int l = 0; l < LL; l++) {
        size_t r = r0 + l;
        float u  = g_xb[r * DI + d];
        float dt = g_dt[r * DI + d];
        const float4* BC = (const float4*)(&g_xdbl[r * 80 + DR]);
        float4 Bv0 = __ldg(&BC[0]), Bv1 = __ldg(&BC[1]);
        float4 Bv2 = __ldg(&BC[2]), Bv3 = __ldg(&BC[3]);
        float4 Cv0 = __ldg(&BC[4]), Cv1 = __ldg(&BC[5]);
        float4 Cv2 = __ldg(&BC[6]), Cv3 = __ldg(&BC[7]);
        float Bl[DS] = {Bv0.x, Bv0.y, Bv0.z, Bv0.w, Bv1.x, Bv1.y, Bv1.z, Bv1.w,
                        Bv2.x, Bv2.y, Bv2.z, Bv2.w, Bv3.x, Bv3.y, Bv3.z, Bv3.w};
        float Cl[DS] = {Cv0.x, Cv0.y, Cv0.z, Cv0.w, Cv1.x, Cv1.y, Cv1.z, Cv1.w,
                        Cv2.x, Cv2.y, Cv2.z, Cv2.w, Cv3.x, Cv3.y, Cv3.z, Cv3.w};

        float du = dt * u;
        float yv = 0.f;
        if (arith) {
            float p  = __expf(dt * a0);
            float rr = __expf(dt * da);
#pragma unroll
            for (int n = 0; n < DS; n++) {
                h[n] = fmaf(p, h[n], du * Bl[n]);
                yv   = fmaf(h[n], Cl[n], yv);
                p *= rr;
            }
        } else {
#pragma unroll
            for (int n = 0; n < DS; n++) {
                float p = __expf(dt * Ar[n]);
                h[n] = fmaf(p, h[n], du * Bl[n]);
                yv   = fmaf(h[n], Cl[n], yv);
            }
        }
        yv = fmaf(u, Dd, yv);
        float z = g_xz[r * (2 * DI) + DI + d];
        g_y[r * DI + d] = yv * siluf_(z);
    }
}

// ---------------------------------------------------------------------------
// host launcher
// ---------------------------------------------------------------------------
extern "C" void kernel_launch(void* const* d_in, const int* in_sizes, int n_in,
                              void* d_out, int out_size) {
    const float* x         = (const float*)d_in[0];
    const float* norm_w    = (const float*)d_in[1];
    const float* in_proj_w = (const float*)d_in[2];   // (2, 3072, 768)
    const float* conv_w    = (const float*)d_in[3];   // (2, 1536, 4)
    const float* conv_b    = (const float*)d_in[4];
    const float* x_proj_w  = (const float*)d_in[5];   // (2, 80, 1536)
    const float* dt_proj_w = (const float*)d_in[6];   // (2, 1536, 48)
    const float* dt_proj_b = (const float*)d_in[7];
    const float* A_log     = (const float*)d_in[8];   // (2, 1536, 16)
    const float* Dp        = (const float*)d_in[9];
    const float* mix_out_w = (const float*)d_in[10];  // (2, 768, 1536)
    const float* gate_w    = (const float*)d_in[11];  // (768, 1536)
    const float* gate_b    = (const float*)d_in[12];
    const float* proj_w    = (const float*)d_in[13];  // (768, 768)
    const float* proj_b    = (const float*)d_in[14];
    float* out = (float*)d_out;

    float *xn, *xz, *xb, *xdbl, *dt, *y, *o_out, *comb;
    cudaGetSymbolAddress((void**)&xn,    g_xn);
    cudaGetSymbolAddress((void**)&xz,    g_xz);
    cudaGetSymbolAddress((void**)&xb,    g_xb);
    cudaGetSymbolAddress((void**)&xdbl,  g_xdbl);
    cudaGetSymbolAddress((void**)&dt,    g_dt);
    cudaGetSymbolAddress((void**)&y,     g_y);
    cudaGetSymbolAddress((void**)&o_out, g_out);
    cudaGetSymbolAddress((void**)&comb,  g_comb);

    setup_A_kernel<<<(2 * DI * DS + 255) / 256, 256>>>(A_log);
    check_arith_kernel<<<1, 256>>>();

    rmsnorm_kernel<<<2 * MM, 256>>>(x, norm_w);

    // in_proj: (1568x768) @ (3072x768)^T -> xz, both dirs in z
    gemm_t<128, 128, 16, EPI_STORE, 1><<<dim3(2 * DI / 128, (MM + 127) / 128, 2), 256>>>(
        xn, CM, (size_t)MM * CM,
        in_proj_w, (size_t)2 * DI * CM,
        xz, 2 * DI, (size_t)MM * 2 * DI,
        MM, 2 * DI, CM, nullptr, 0, nullptr);

    conv_silu_kernel<<<(2 * MM * DI + 255) / 256, 256>>>(conv_w, conv_b);

    // x_proj: (1568x1536) @ (80x1536)^T -> xdbl, split-K=8, atomic accumulate
    cudaMemsetAsync(xdbl, 0, sizeof(float) * 2 * MM * 80);
    gemm_t<128, 80, 16, EPI_STORE, 8><<<dim3(1, (MM + 127) / 128, 2 * 8), 256>>>(
        xb, DI, (size_t)MM * DI,
        x_proj_w, (size_t)80 * DI,
        xdbl, 80, (size_t)MM * 80,
        MM, 80, DI, nullptr, 0, nullptr);

    // dt_proj + softplus: (1568x48) @ (1536x48)^T -> dt
    gemm_t<128, 128, 16, EPI_SOFTPLUS, 1><<<dim3(DI / 128, (MM + 127) / 128, 2), 256>>>(
        xdbl, 80, (size_t)MM * 80,
        dt_proj_w, (size_t)DI * DR,
        dt, DI, (size_t)MM * DI,
        MM, DI, DR, dt_proj_b, DI, nullptr);

    // selective scan + y*silu(z)
    scan_kernel<<<dim3(DI / 128, BB, 2), 128>>>(Dp);

    // out_proj + residual + flip-scatter -> g_out interleaved, both dirs
    gemm_t<128, 64, 16, EPI_RESID, 1><<<dim3(CM / 64, (MM + 127) / 128, 2), 256>>>(
        y, DI, (size_t)MM * DI,
        mix_out_w, (size_t)CM * DI,
        o_out, 0, 0,
        MM, CM, DI, nullptr, 0, x);

    // gate GEMM + sigmoid combine -> comb
    gemm_t<128, 64, 16, EPI_GATE, 1><<<dim3(CM / 64, (MM + 127) / 128, 1), 256>>>(
        o_out, 2 * CM, 0,
        gate_w, 0,
        comb, CM, 0,
        MM, CM, 2 * CM, gate_b, 0, o_out);

    // final projection + bias -> d_out
    gemm_t<128, 64, 16, EPI_BIAS, 1><<<dim3(CM / 64, (MM + 127) / 128, 1), 256>>>(
        comb, CM, 0,
        proj_w, 0,
        out, CM, 0,
        MM, CM, CM, proj_b, 0, nullptr);

    (void)in_sizes; (void)n_in; (void)out_size;
}